// round 4
// baseline (speedup 1.0000x reference)
#include <cuda_runtime.h>
#include <cstdint>
#include <cstddef>

// Problem dims
#define B_   256
#define IV   1000
#define D_   800
#define H1_  256
#define H2_  16
#define PH_  256

// Tiling
#define DK   16            // K-chunk staged in SMEM
#define IT   64            // intervals per CTA tile
#define GRID_I ((IV + IT - 1) / IT)   // 16

// Inter-kernel scratch: fc_input [B, IV]  (1 MB, static __device__ -> legal)
__device__ float g_fc[B_ * IV];

// Packed fp32x2 FMA (PTX-only on sm_103a; doubles fp32 throughput)
#define PACK2(out, lo, hi) \
    asm("mov.b64 %0, {%1, %2};" : "=l"(out) : "r"(lo), "r"(hi))
#define UNPACK2(lo, hi, in) \
    asm("mov.b64 {%0, %1}, %2;" : "=r"(lo), "=r"(hi) : "l"(in))
#define FMA2(d, a, b, c) \
    asm("fma.rn.f32x2 %0, %1, %2, %3;" : "=l"(d) : "l"(a), "l"(b), "l"(c))

// Dynamic SMEM layout (float offsets)
#define OFF_WS    0                    // [DK][256]   W1 chunk, d-major      (16 KB)
#define OFF_SS    4096                 // [DK][IT]    state chunk            (4 KB)   (reused as H2s[16][64])
#define OFF_W2S   5120                 // [16][256]   W2                     (16 KB)
#define OFF_B1S   9216                 // [256]
#define OFF_B2S   9472                 // [16]
#define OFF_W3S   9488                 // [16]
#define OFF_B3    9504                 // [1], pad to 9536
#define OFF_H1S   9536                 // [IT][260]   h1 tile, i-major, padded stride (conflict-free LDS.128)
#define H1S_STRIDE 260
#define SMEM_FLOATS (OFF_H1S + IT * H1S_STRIDE)     // 26176
#define SMEM_BYTES  (SMEM_FLOATS * 4)               // 104704 B -> 2 CTAs/SM

// ---------------------------------------------------------------------------
// Kernel 1: fused  relu(W1 @ S + b1) -> relu(W2 @ . + b2) -> W3 @ . + b3
// Grid: (GRID_I, B).  Block: 256 threads.
// Per CTA: C tile [256 h  x  64 i] for one batch, K=800 in DK=16 chunks.
// Thread tile: 16 h (as 8 f32x2 pairs) x 4 i  => 32 packed accumulators.
// ---------------------------------------------------------------------------
__global__ __launch_bounds__(256, 2)
void section_kernel(const float* __restrict__ state,
                    const float* __restrict__ W1, const float* __restrict__ b1,
                    const float* __restrict__ W2, const float* __restrict__ b2,
                    const float* __restrict__ W3, const float* __restrict__ b3)
{
    extern __shared__ float sm[];
    float* Ws  = sm + OFF_WS;     // Ws[d][h]
    float* Ss  = sm + OFF_SS;     // Ss[d][i]
    float* W2s = sm + OFF_W2S;    // W2s[g][h]
    float* b1s = sm + OFF_B1S;
    float* b2s = sm + OFF_B2S;
    float* w3s = sm + OFF_W3S;
    float* h1s = sm + OFF_H1S;    // h1s[i][h], stride 260

    const int tid = threadIdx.x;
    const int b   = blockIdx.y;
    const int i0  = blockIdx.x * IT;

    // ---- one-time staging of small tensors ----
    for (int idx = tid; idx < H2_ * H1_; idx += 256) W2s[idx] = W2[idx];
    if (tid < 256) b1s[tid] = b1[tid];
    if (tid < 16)  { b2s[tid] = b2[tid]; w3s[tid] = W3[tid]; }
    if (tid == 0)  sm[OFF_B3] = b3[0];

    const float* Sb = state + (size_t)b * (D_ * IV);

    // staging index precompute
    const int wh  = tid >> 2;         // h base lane for W loads (0..63, x4 iters)
    const int wdv = tid & 3;          // which 4-d group within chunk
    const int sdd = tid >> 4;         // d row for S loads (0..15)
    const int sii = (tid & 15) * 4;   // i offset (vec4)
    const int sgi = i0 + sii;
    const bool svalid = (sgi < IV);   // IV % 4 == 0 -> whole-vec4 validity

    float4 wreg[4];
    float4 sreg = make_float4(0.f, 0.f, 0.f, 0.f);

    // prologue: prefetch chunk 0 into registers
    {
        #pragma unroll
        for (int r = 0; r < 4; r++)
            wreg[r] = *(const float4*)(W1 + (r * 64 + wh) * D_ + wdv * 4);
        if (svalid)
            sreg = *(const float4*)(Sb + sdd * IV + sgi);
    }

    unsigned long long acc[8][4];
    #pragma unroll
    for (int hp = 0; hp < 8; hp++)
        #pragma unroll
        for (int ii = 0; ii < 4; ii++)
            acc[hp][ii] = 0ull;       // bits of (0.f, 0.f)

    const int hb = (tid >> 4) * 16;   // h base of this thread's 16-h strip
    const int ib = (tid & 15) * 4;    // i base of this thread's 4 intervals

    // ---- main K loop: stage(regs->smem) | prefetch next | compute ----
    for (int k0 = 0; k0 < D_; k0 += DK) {
        __syncthreads();              // prior compute done before overwrite
        #pragma unroll
        for (int r = 0; r < 4; r++) {
            const int h  = r * 64 + wh;
            const int db = wdv * 4;
            Ws[(db + 0) * H1_ + h] = wreg[r].x;
            Ws[(db + 1) * H1_ + h] = wreg[r].y;
            Ws[(db + 2) * H1_ + h] = wreg[r].z;
            Ws[(db + 3) * H1_ + h] = wreg[r].w;
        }
        *(float4*)(Ss + sdd * IT + sii) = sreg;
        __syncthreads();

        const int kn = k0 + DK;
        if (kn < D_) {                // prefetch next chunk (overlaps compute)
            #pragma unroll
            for (int r = 0; r < 4; r++)
                wreg[r] = *(const float4*)(W1 + (r * 64 + wh) * D_ + kn + wdv * 4);
            if (svalid)
                sreg = *(const float4*)(Sb + (kn + sdd) * IV + sgi);
        }

        #pragma unroll
        for (int dd = 0; dd < DK; dd++) {
            const float4 x = *(const float4*)(Ss + dd * IT + ib);
            unsigned long long xx0, xx1, xx2, xx3;
            { unsigned u = __float_as_uint(x.x); PACK2(xx0, u, u); }
            { unsigned u = __float_as_uint(x.y); PACK2(xx1, u, u); }
            { unsigned u = __float_as_uint(x.z); PACK2(xx2, u, u); }
            { unsigned u = __float_as_uint(x.w); PACK2(xx3, u, u); }
            const unsigned long long* wr =
                (const unsigned long long*)(Ws + dd * H1_ + hb);   // 8 h-pairs
            #pragma unroll
            for (int hp = 0; hp < 8; hp++) {
                const unsigned long long w = wr[hp];
                FMA2(acc[hp][0], w, xx0, acc[hp][0]);
                FMA2(acc[hp][1], w, xx1, acc[hp][1]);
                FMA2(acc[hp][2], w, xx2, acc[hp][2]);
                FMA2(acc[hp][3], w, xx3, acc[hp][3]);
            }
        }
    }

    // ---- epilogue: bias+relu -> h1s[i][h] ----
    #pragma unroll
    for (int hp = 0; hp < 8; hp++) {
        const int h0 = hb + hp * 2;
        const float bl = b1s[h0], bh = b1s[h0 + 1];
        #pragma unroll
        for (int ii = 0; ii < 4; ii++) {
            unsigned lo, hi;
            UNPACK2(lo, hi, acc[hp][ii]);
            float flo = fmaxf(__uint_as_float(lo) + bl, 0.f);
            float fhi = fmaxf(__uint_as_float(hi) + bh, 0.f);
            float* row = h1s + (ib + ii) * H1S_STRIDE;
            row[h0]     = flo;
            row[h0 + 1] = fhi;
        }
    }
    __syncthreads();   // all mainloop compute + h1 stores visible

    // ---- layer 2: H2[g][i] = relu(W2 @ h1 + b2), 256 threads = (4 g) x (64 i) ----
    {
        const int li = tid & 63;
        const int gq = tid >> 6;      // 0..3 -> g = gq*4 + j
        float a2[4] = { b2s[gq * 4 + 0], b2s[gq * 4 + 1],
                        b2s[gq * 4 + 2], b2s[gq * 4 + 3] };
        const float4* xr = (const float4*)(h1s + li * H1S_STRIDE);
        #pragma unroll 8
        for (int hv = 0; hv < H1_ / 4; hv++) {
            const float4 x = xr[hv];
            #pragma unroll
            for (int j = 0; j < 4; j++) {
                const float4 w = *(const float4*)(W2s + (gq * 4 + j) * H1_ + hv * 4);
                a2[j] += x.x * w.x + x.y * w.y + x.z * w.z + x.w * w.w;
            }
        }
        #pragma unroll
        for (int j = 0; j < 4; j++)
            Ss[(gq * 4 + j) * IT + li] = fmaxf(a2[j], 0.f);   // reuse Ss as H2s[16][64]
    }
    __syncthreads();

    // ---- layer 3: sec[i] = W3 @ H2 + b3 -> g_fc ----
    if (tid < IT) {
        float sec = sm[OFF_B3];
        #pragma unroll
        for (int g = 0; g < H2_; g++)
            sec += w3s[g] * Ss[g * IT + tid];
        const int gi = i0 + tid;
        if (gi < IV)
            g_fc[b * IV + gi] = sec;
    }
}

// ---------------------------------------------------------------------------
// Kernel 2: val[b] = Wv @ relu(Wp @ fc[b] + bp) + bv
// Grid: B blocks, 256 threads (one per PRED_H row), then block reduction.
// ---------------------------------------------------------------------------
__global__ __launch_bounds__(256)
void pred_kernel(const float* __restrict__ Wp, const float* __restrict__ bp,
                 const float* __restrict__ Wv, const float* __restrict__ bv,
                 float* __restrict__ out)
{
    __shared__ float fcb[IV];
    __shared__ float red[256];
    const int b   = blockIdx.x;
    const int tid = threadIdx.x;

    const float* f = g_fc + b * IV;
    for (int idx = tid; idx < IV; idx += 256) fcb[idx] = f[idx];
    __syncthreads();

    float acc = 0.f;
    const float4* wr = (const float4*)(Wp + tid * IV);
    #pragma unroll 5
    for (int kv = 0; kv < IV / 4; kv++) {
        const float4 w = wr[kv];
        const float4 x = *(const float4*)(fcb + kv * 4);
        acc += w.x * x.x + w.y * x.y + w.z * x.z + w.w * x.w;
    }
    const float y = fmaxf(acc + bp[tid], 0.f);
    red[tid] = y * Wv[tid];
    __syncthreads();
    for (int s = 128; s > 0; s >>= 1) {
        if (tid < s) red[tid] += red[tid + s];
        __syncthreads();
    }
    if (tid == 0) out[b] = red[0] + bv[0];
}

// ---------------------------------------------------------------------------
extern "C" void kernel_launch(void* const* d_in, const int* in_sizes, int n_in,
                              void* d_out, int out_size)
{
    const float* state = (const float*)d_in[0];
    const float* W1    = (const float*)d_in[1];
    const float* b1    = (const float*)d_in[2];
    const float* W2    = (const float*)d_in[3];
    const float* b2    = (const float*)d_in[4];
    const float* W3    = (const float*)d_in[5];
    const float* b3    = (const float*)d_in[6];
    const float* Wp    = (const float*)d_in[7];
    const float* bp    = (const float*)d_in[8];
    const float* Wv    = (const float*)d_in[9];
    const float* bv    = (const float*)d_in[10];
    float* out = (float*)d_out;

    // 104.7 KB dynamic SMEM (> 48 KB static limit) -> opt in every call
    // (idempotent, host-side, not a stream op: graph-capture safe)
    cudaFuncSetAttribute(section_kernel,
                         cudaFuncAttributeMaxDynamicSharedMemorySize, SMEM_BYTES);

    dim3 grid(GRID_I, B_);
    section_kernel<<<grid, 256, SMEM_BYTES>>>(state, W1, b1, W2, b2, W3, b3);
    pred_kernel<<<B_, 256>>>(Wp, bp, Wv, bv, out);
}

// round 5
// speedup vs baseline: 1.0002x; 1.0002x over previous
#include <cuda_runtime.h>
#include <cstdint>
#include <cstddef>

// Problem dims
#define B_   256
#define IV   1000
#define D_   800
#define H1_  256
#define H2_  16
#define PH_  256

// Tiling
#define DK   16            // K-chunk staged in SMEM
#define IT   64            // intervals per CTA tile
#define GRID_I ((IV + IT - 1) / IT)   // 16

// Inter-kernel scratch: fc_input [B, IV]  (1 MB, static __device__ -> legal)
__device__ float g_fc[B_ * IV];

// Packed fp32x2 FMA (PTX-only on sm_103a; doubles fp32 throughput)
#define PACK2(out, lo, hi) \
    asm("mov.b64 %0, {%1, %2};" : "=l"(out) : "r"(lo), "r"(hi))
#define UNPACK2(lo, hi, in) \
    asm("mov.b64 {%0, %1}, %2;" : "=r"(lo), "=r"(hi) : "l"(in))
#define FMA2(d, a, b, c) \
    asm("fma.rn.f32x2 %0, %1, %2, %3;" : "=l"(d) : "l"(a), "l"(b), "l"(c))

// Dynamic SMEM layout (float offsets)
#define OFF_WS    0                    // [DK][256]   W1 chunk, d-major      (16 KB)
#define OFF_SS    4096                 // [DK][IT]    state chunk            (4 KB)   (reused as H2s[16][64])
#define OFF_W2S   5120                 // [16][256]   W2                     (16 KB)
#define OFF_B1S   9216                 // [256]
#define OFF_B2S   9472                 // [16]
#define OFF_W3S   9488                 // [16]
#define OFF_B3    9504                 // [1], pad to 9536
#define OFF_H1S   9536                 // [IT][260]   h1 tile, i-major, padded stride (conflict-free LDS.128)
#define H1S_STRIDE 260
#define SMEM_FLOATS (OFF_H1S + IT * H1S_STRIDE)     // 26176
#define SMEM_BYTES  (SMEM_FLOATS * 4)               // 104704 B -> 2 CTAs/SM

// ---------------------------------------------------------------------------
// Kernel 1: fused  relu(W1 @ S + b1) -> relu(W2 @ . + b2) -> W3 @ . + b3
// Grid: (GRID_I, B).  Block: 256 threads.
// Per CTA: C tile [256 h  x  64 i] for one batch, K=800 in DK=16 chunks.
// Thread tile: 16 h (as 8 f32x2 pairs) x 4 i  => 32 packed accumulators.
// ---------------------------------------------------------------------------
__global__ __launch_bounds__(256, 2)
void section_kernel(const float* __restrict__ state,
                    const float* __restrict__ W1, const float* __restrict__ b1,
                    const float* __restrict__ W2, const float* __restrict__ b2,
                    const float* __restrict__ W3, const float* __restrict__ b3)
{
    extern __shared__ float sm[];
    float* Ws  = sm + OFF_WS;     // Ws[d][h]
    float* Ss  = sm + OFF_SS;     // Ss[d][i]
    float* W2s = sm + OFF_W2S;    // W2s[g][h]
    float* b1s = sm + OFF_B1S;
    float* b2s = sm + OFF_B2S;
    float* w3s = sm + OFF_W3S;
    float* h1s = sm + OFF_H1S;    // h1s[i][h], stride 260

    const int tid = threadIdx.x;
    const int b   = blockIdx.y;
    const int i0  = blockIdx.x * IT;

    // ---- one-time staging of small tensors ----
    for (int idx = tid; idx < H2_ * H1_; idx += 256) W2s[idx] = W2[idx];
    if (tid < 256) b1s[tid] = b1[tid];
    if (tid < 16)  { b2s[tid] = b2[tid]; w3s[tid] = W3[tid]; }
    if (tid == 0)  sm[OFF_B3] = b3[0];

    const float* Sb = state + (size_t)b * (D_ * IV);

    // staging index precompute
    const int wh  = tid >> 2;         // h base lane for W loads (0..63, x4 iters)
    const int wdv = tid & 3;          // which 4-d group within chunk
    const int sdd = tid >> 4;         // d row for S loads (0..15)
    const int sii = (tid & 15) * 4;   // i offset (vec4)
    const int sgi = i0 + sii;
    const bool svalid = (sgi < IV);   // IV % 4 == 0 -> whole-vec4 validity

    float4 wreg[4];
    float4 sreg = make_float4(0.f, 0.f, 0.f, 0.f);

    // prologue: prefetch chunk 0 into registers
    {
        #pragma unroll
        for (int r = 0; r < 4; r++)
            wreg[r] = *(const float4*)(W1 + (r * 64 + wh) * D_ + wdv * 4);
        if (svalid)
            sreg = *(const float4*)(Sb + sdd * IV + sgi);
    }

    unsigned long long acc[8][4];
    #pragma unroll
    for (int hp = 0; hp < 8; hp++)
        #pragma unroll
        for (int ii = 0; ii < 4; ii++)
            acc[hp][ii] = 0ull;       // bits of (0.f, 0.f)

    const int hb = (tid >> 4) * 16;   // h base of this thread's 16-h strip
    const int ib = (tid & 15) * 4;    // i base of this thread's 4 intervals

    // ---- main K loop: stage(regs->smem) | prefetch next | compute ----
    for (int k0 = 0; k0 < D_; k0 += DK) {
        __syncthreads();              // prior compute done before overwrite
        #pragma unroll
        for (int r = 0; r < 4; r++) {
            const int h  = r * 64 + wh;
            const int db = wdv * 4;
            Ws[(db + 0) * H1_ + h] = wreg[r].x;
            Ws[(db + 1) * H1_ + h] = wreg[r].y;
            Ws[(db + 2) * H1_ + h] = wreg[r].z;
            Ws[(db + 3) * H1_ + h] = wreg[r].w;
        }
        *(float4*)(Ss + sdd * IT + sii) = sreg;
        __syncthreads();

        const int kn = k0 + DK;
        if (kn < D_) {                // prefetch next chunk (overlaps compute)
            #pragma unroll
            for (int r = 0; r < 4; r++)
                wreg[r] = *(const float4*)(W1 + (r * 64 + wh) * D_ + kn + wdv * 4);
            if (svalid)
                sreg = *(const float4*)(Sb + (kn + sdd) * IV + sgi);
        }

        #pragma unroll
        for (int dd = 0; dd < DK; dd++) {
            const float4 x = *(const float4*)(Ss + dd * IT + ib);
            unsigned long long xx0, xx1, xx2, xx3;
            { unsigned u = __float_as_uint(x.x); PACK2(xx0, u, u); }
            { unsigned u = __float_as_uint(x.y); PACK2(xx1, u, u); }
            { unsigned u = __float_as_uint(x.z); PACK2(xx2, u, u); }
            { unsigned u = __float_as_uint(x.w); PACK2(xx3, u, u); }
            const unsigned long long* wr =
                (const unsigned long long*)(Ws + dd * H1_ + hb);   // 8 h-pairs
            #pragma unroll
            for (int hp = 0; hp < 8; hp++) {
                const unsigned long long w = wr[hp];
                FMA2(acc[hp][0], w, xx0, acc[hp][0]);
                FMA2(acc[hp][1], w, xx1, acc[hp][1]);
                FMA2(acc[hp][2], w, xx2, acc[hp][2]);
                FMA2(acc[hp][3], w, xx3, acc[hp][3]);
            }
        }
    }

    // ---- epilogue: bias+relu -> h1s[i][h] ----
    #pragma unroll
    for (int hp = 0; hp < 8; hp++) {
        const int h0 = hb + hp * 2;
        const float bl = b1s[h0], bh = b1s[h0 + 1];
        #pragma unroll
        for (int ii = 0; ii < 4; ii++) {
            unsigned lo, hi;
            UNPACK2(lo, hi, acc[hp][ii]);
            float flo = fmaxf(__uint_as_float(lo) + bl, 0.f);
            float fhi = fmaxf(__uint_as_float(hi) + bh, 0.f);
            float* row = h1s + (ib + ii) * H1S_STRIDE;
            row[h0]     = flo;
            row[h0 + 1] = fhi;
        }
    }
    __syncthreads();   // all mainloop compute + h1 stores visible

    // ---- layer 2: H2[g][i] = relu(W2 @ h1 + b2), 256 threads = (4 g) x (64 i) ----
    {
        const int li = tid & 63;
        const int gq = tid >> 6;      // 0..3 -> g = gq*4 + j
        float a2[4] = { b2s[gq * 4 + 0], b2s[gq * 4 + 1],
                        b2s[gq * 4 + 2], b2s[gq * 4 + 3] };
        const float4* xr = (const float4*)(h1s + li * H1S_STRIDE);
        #pragma unroll 8
        for (int hv = 0; hv < H1_ / 4; hv++) {
            const float4 x = xr[hv];
            #pragma unroll
            for (int j = 0; j < 4; j++) {
                const float4 w = *(const float4*)(W2s + (gq * 4 + j) * H1_ + hv * 4);
                a2[j] += x.x * w.x + x.y * w.y + x.z * w.z + x.w * w.w;
            }
        }
        #pragma unroll
        for (int j = 0; j < 4; j++)
            Ss[(gq * 4 + j) * IT + li] = fmaxf(a2[j], 0.f);   // reuse Ss as H2s[16][64]
    }
    __syncthreads();

    // ---- layer 3: sec[i] = W3 @ H2 + b3 -> g_fc ----
    if (tid < IT) {
        float sec = sm[OFF_B3];
        #pragma unroll
        for (int g = 0; g < H2_; g++)
            sec += w3s[g] * Ss[g * IT + tid];
        const int gi = i0 + tid;
        if (gi < IV)
            g_fc[b * IV + gi] = sec;
    }
}

// ---------------------------------------------------------------------------
// Kernel 2: val[b] = Wv @ relu(Wp @ fc[b] + bp) + bv
// Grid: B blocks, 256 threads (one per PRED_H row), then block reduction.
// ---------------------------------------------------------------------------
__global__ __launch_bounds__(256)
void pred_kernel(const float* __restrict__ Wp, const float* __restrict__ bp,
                 const float* __restrict__ Wv, const float* __restrict__ bv,
                 float* __restrict__ out)
{
    __shared__ float fcb[IV];
    __shared__ float red[256];
    const int b   = blockIdx.x;
    const int tid = threadIdx.x;

    const float* f = g_fc + b * IV;
    for (int idx = tid; idx < IV; idx += 256) fcb[idx] = f[idx];
    __syncthreads();

    float acc = 0.f;
    const float4* wr = (const float4*)(Wp + tid * IV);
    #pragma unroll 5
    for (int kv = 0; kv < IV / 4; kv++) {
        const float4 w = wr[kv];
        const float4 x = *(const float4*)(fcb + kv * 4);
        acc += w.x * x.x + w.y * x.y + w.z * x.z + w.w * x.w;
    }
    const float y = fmaxf(acc + bp[tid], 0.f);
    red[tid] = y * Wv[tid];
    __syncthreads();
    for (int s = 128; s > 0; s >>= 1) {
        if (tid < s) red[tid] += red[tid + s];
        __syncthreads();
    }
    if (tid == 0) out[b] = red[0] + bv[0];
}

// ---------------------------------------------------------------------------
extern "C" void kernel_launch(void* const* d_in, const int* in_sizes, int n_in,
                              void* d_out, int out_size)
{
    const float* state = (const float*)d_in[0];
    const float* W1    = (const float*)d_in[1];
    const float* b1    = (const float*)d_in[2];
    const float* W2    = (const float*)d_in[3];
    const float* b2    = (const float*)d_in[4];
    const float* W3    = (const float*)d_in[5];
    const float* b3    = (const float*)d_in[6];
    const float* Wp    = (const float*)d_in[7];
    const float* bp    = (const float*)d_in[8];
    const float* Wv    = (const float*)d_in[9];
    const float* bv    = (const float*)d_in[10];
    float* out = (float*)d_out;

    // 104.7 KB dynamic SMEM (> 48 KB static limit) -> opt in every call
    // (idempotent, host-side, not a stream op: graph-capture safe)
    cudaFuncSetAttribute(section_kernel,
                         cudaFuncAttributeMaxDynamicSharedMemorySize, SMEM_BYTES);

    dim3 grid(GRID_I, B_);
    section_kernel<<<grid, 256, SMEM_BYTES>>>(state, W1, b1, W2, b2, W3, b3);
    pred_kernel<<<B_, 256>>>(Wp, bp, Wv, bv, out);
}